// round 5
// baseline (speedup 1.0000x reference)
#include <cuda_runtime.h>
#include <cuda_bf16.h>
#include <cstdint>

#define BB 8
#define CC 64
#define NN 4096
#define KK 16
#define EE 64
#define NPOINTS (BB*NN)            // 32768
#define CNT1 524288.0f             // B*N*K
#define CNT3 32768.0f              // B*N
#define EPSV 1e-5f

// ---- scratch (device globals: allocation-free rule) ----
__device__ float g_y1t[NPOINTS*EE];       // 8 MB  u = a1 * y after k_prep
__device__ float g_un[NPOINTS*EE];        // 8 MB  un' = u - c1
__device__ float g_zmax[NPOINTS*EE];      // 8 MB
__device__ float g_zmin[NPOINTS*EE];      // 8 MB
__device__ float g_sum1[EE], g_sumsq1[EE];
__device__ float g_sum2[EE], g_sumsq2[EE];
__device__ float g_sum3[EE], g_sumsq3[EE];

// pack two fp32 into bf16x2 (lo in low half, hi in high half)
__device__ __forceinline__ uint32_t pack_bf2(float lo_e, float hi_e) {
    uint32_t r;
    asm("cvt.rn.bf16x2.f32 %0, %1, %2;" : "=r"(r) : "f"(hi_e), "f"(lo_e));
    return r;
}

__device__ __forceinline__ void mma16816(float d[4], const uint32_t a[4], const uint32_t b[2]) {
    asm volatile(
        "mma.sync.aligned.m16n8k16.row.col.f32.bf16.bf16.f32 "
        "{%0,%1,%2,%3}, {%4,%5,%6,%7}, {%8,%9}, {%0,%1,%2,%3};"
        : "+f"(d[0]), "+f"(d[1]), "+f"(d[2]), "+f"(d[3])
        : "r"(a[0]), "r"(a[1]), "r"(a[2]), "r"(a[3]), "r"(b[0]), "r"(b[1]));
}

// split a packed pair (x,y) into hi (bf16) and lo (residual bf16)
__device__ __forceinline__ void split2(float x, float y, uint32_t& hi, uint32_t& lo) {
    hi = pack_bf2(x, y);
    float e0 = __uint_as_float(hi << 16);
    float e1 = __uint_as_float(hi & 0xffff0000u);
    lo = pack_bf2(x - e0, y - e1);
}

// ============================================================================
// y1t[b][n][e] = sum_c W1[e][c] * x[b][c][n];  block(0,0) zeroes accumulators
__global__ void k_y1(const float* __restrict__ x, const float* __restrict__ W1) {
    __shared__ float xs[CC][64];
    __shared__ float W1sT[CC][EE];
    int b = blockIdx.y;
    int n0 = blockIdx.x * 64;
    int t = threadIdx.x;
    if (blockIdx.x == 0 && blockIdx.y == 0 && t < EE) {
        g_sum1[t]=0.f; g_sumsq1[t]=0.f;
        g_sum2[t]=0.f; g_sumsq2[t]=0.f;
        g_sum3[t]=0.f; g_sumsq3[t]=0.f;
    }
    for (int i = t; i < CC*EE; i += 256) {
        int o = i >> 6, c = i & 63;
        W1sT[c][o] = W1[i];
    }
    for (int i = t; i < CC*64; i += 256) {
        int c = i >> 6, j = i & 63;
        xs[c][j] = x[(b*CC + c)*NN + n0 + j];
    }
    __syncthreads();
    int e = t & 63;
    int nb = (t >> 6) * 16;
    float acc[16];
    #pragma unroll
    for (int i = 0; i < 16; i++) acc[i] = 0.f;
    #pragma unroll 4
    for (int c = 0; c < CC; c++) {
        float w = W1sT[c][e];
        #pragma unroll
        for (int i = 0; i < 16; i++) acc[i] = fmaf(w, xs[c][nb+i], acc[i]);
    }
    #pragma unroll
    for (int i = 0; i < 16; i++)
        g_y1t[(b*NN + n0 + nb + i)*EE + e] = acc[i];
}

// BN1 stats over d = y_j - y_n
__global__ void k_stats1(const int* __restrict__ idx) {
    __shared__ float red[4][64];
    int t = threadIdx.x;
    int c = t & 63, g = t >> 6;
    float s = 0.f, q = 0.f;
    int p0 = blockIdx.x * 64;
    for (int pl = g; pl < 64; pl += 4) {
        int point = p0 + pl;
        int brow = (point >> 12) << 12;
        float yn = g_y1t[point*EE + c];
        const int* ip = idx + point*KK;
        #pragma unroll
        for (int k = 0; k < KK; k++) {
            int j = ip[k];
            float yj = g_y1t[(brow + j)*EE + c];
            float d = yj - yn;
            s += d;
            q = fmaf(d, d, q);
        }
    }
    red[g][c] = s;
    __syncthreads();
    if (g == 0) atomicAdd(&g_sum1[c], red[0][c]+red[1][c]+red[2][c]+red[3][c]);
    __syncthreads();
    red[g][c] = q;
    __syncthreads();
    if (g == 0) atomicAdd(&g_sumsq1[c], red[0][c]+red[1][c]+red[2][c]+red[3][c]);
}

// fold BN1 into y: u = a1*y (in place), un' = u - c1
__global__ void k_prep(const float* __restrict__ g1, const float* __restrict__ be1) {
    int i = blockIdx.x * blockDim.x + threadIdx.x;   // float4 index, 524288 total
    int c0 = (i & 15) * 4;
    float a[4], cv[4];
    #pragma unroll
    for (int j = 0; j < 4; j++) {
        int c = c0 + j;
        float m1 = g_sum1[c] * (1.f/CNT1);
        float v1 = fmaxf(g_sumsq1[c] * (1.f/CNT1) - m1*m1, 0.f);
        a[j] = g1[c] * rsqrtf(v1 + EPSV);
        cv[j] = be1[c] - a[j] * m1;
    }
    float4* Y = (float4*)g_y1t;
    float4* U = (float4*)g_un;
    float4 v = Y[i];
    v.x *= a[0]; v.y *= a[1]; v.z *= a[2]; v.w *= a[3];
    Y[i] = v;
    float4 u;
    u.x = v.x - cv[0]; u.y = v.y - cv[1]; u.z = v.z - cv[2]; u.w = v.w - cv[3];
    U[i] = u;
}

// ============================================================================
// Main pass via mma.sync bf16 (split-bf16, 3 terms). One warp = one point.
// M=16 neighbors, N=64 out channels (8 n-tiles), K=64 in channels (4 k-steps).
__global__ void __launch_bounds__(128) k_edge(const int* __restrict__ idx,
                                              const float* __restrict__ W2) {
    __shared__ float sm_s[64], sm_q[64];
    int t = threadIdx.x;
    if (t < 64) { sm_s[t] = 0.f; sm_q[t] = 0.f; }
    __syncthreads();

    int lane = t & 31, w = t >> 5;
    int g = lane >> 2, q = lane & 3;

    // B fragments (W2^T as col-major k x n): resident hi/lo
    uint32_t Bhi[8][4][2], Blo[8][4][2];
    #pragma unroll
    for (int nt = 0; nt < 8; nt++) {
        int n = nt*8 + g;
        #pragma unroll
        for (int ks = 0; ks < 4; ks++) {
            const float2* wp = (const float2*)(W2 + n*64 + ks*16 + q*2);
            float2 w0 = wp[0];     // k, k+1
            float2 w1 = wp[4];     // k+8, k+9
            split2(w0.x, w0.y, Bhi[nt][ks][0], Blo[nt][ks][0]);
            split2(w1.x, w1.y, Bhi[nt][ks][1], Blo[nt][ks][1]);
        }
    }

    float sums[16], sumq[16];
    #pragma unroll
    for (int i = 0; i < 16; i++) { sums[i] = 0.f; sumq[i] = 0.f; }

    int wg = blockIdx.x * 4 + w;
    #pragma unroll 1
    for (int pi = 0; pi < 4; pi++) {
        int p = wg * 4 + pi;
        int base = (p >> 12) << 12;
        int j0 = idx[p*KK + g];
        int j1 = idx[p*KK + 8 + g];
        const float* un = g_un  + (size_t)p * EE;
        const float* u0 = g_y1t + (size_t)(base + j0) * EE;
        const float* u1 = g_y1t + (size_t)(base + j1) * EE;

        float D[8][4];
        #pragma unroll
        for (int nt = 0; nt < 8; nt++)
            #pragma unroll
            for (int i = 0; i < 4; i++) D[nt][i] = 0.f;

        #pragma unroll
        for (int ks = 0; ks < 4; ks++) {
            int c0 = ks*16 + q*2;
            float2 n0  = *(const float2*)(un + c0);
            float2 n1  = *(const float2*)(un + c0 + 8);
            float2 x00 = *(const float2*)(u0 + c0);
            float2 x01 = *(const float2*)(u0 + c0 + 8);
            float2 x10 = *(const float2*)(u1 + c0);
            float2 x11 = *(const float2*)(u1 + c0 + 8);
            // h = relu(u_j - un')
            float h00 = fmaxf(x00.x - n0.x, 0.f), h01 = fmaxf(x00.y - n0.y, 0.f);
            float h10 = fmaxf(x10.x - n0.x, 0.f), h11 = fmaxf(x10.y - n0.y, 0.f);
            float h02 = fmaxf(x01.x - n1.x, 0.f), h03 = fmaxf(x01.y - n1.y, 0.f);
            float h12 = fmaxf(x11.x - n1.x, 0.f), h13 = fmaxf(x11.y - n1.y, 0.f);
            uint32_t Ahi[4], Alo[4];
            split2(h00, h01, Ahi[0], Alo[0]);   // row g,   cols c0,c0+1
            split2(h10, h11, Ahi[1], Alo[1]);   // row g+8, cols c0,c0+1
            split2(h02, h03, Ahi[2], Alo[2]);   // row g,   cols c0+8,c0+9
            split2(h12, h13, Ahi[3], Alo[3]);   // row g+8, cols c0+8,c0+9
            #pragma unroll
            for (int nt = 0; nt < 8; nt++) {
                mma16816(D[nt], Ahi, Bhi[nt][ks]);
                mma16816(D[nt], Alo, Bhi[nt][ks]);
                mma16816(D[nt], Ahi, Blo[nt][ks]);
            }
        }

        // reduce over the 16 neighbors (rows)
        #pragma unroll
        for (int nt = 0; nt < 8; nt++) {
            float d0 = D[nt][0], d1 = D[nt][1], d2 = D[nt][2], d3 = D[nt][3];
            sums[nt*2]   += d0 + d2;
            sums[nt*2+1] += d1 + d3;
            sumq[nt*2]   = fmaf(d0, d0, fmaf(d2, d2, sumq[nt*2]));
            sumq[nt*2+1] = fmaf(d1, d1, fmaf(d3, d3, sumq[nt*2+1]));
            float mx0 = fmaxf(d0, d2), mn0 = fminf(d0, d2);
            float mx1 = fmaxf(d1, d3), mn1 = fminf(d1, d3);
            #pragma unroll
            for (int off = 4; off < 32; off <<= 1) {
                mx0 = fmaxf(mx0, __shfl_xor_sync(0xffffffffu, mx0, off));
                mn0 = fminf(mn0, __shfl_xor_sync(0xffffffffu, mn0, off));
                mx1 = fmaxf(mx1, __shfl_xor_sync(0xffffffffu, mx1, off));
                mn1 = fminf(mn1, __shfl_xor_sync(0xffffffffu, mn1, off));
            }
            if (g == 0) {
                size_t o = (size_t)p*EE + nt*8 + q*2;
                *(float2*)(g_zmax + o) = make_float2(mx0, mx1);
                *(float2*)(g_zmin + o) = make_float2(mn0, mn1);
            }
        }
    }

    // BN2 partial sums: smem reduce, then one global atomic per channel
    #pragma unroll
    for (int nt = 0; nt < 8; nt++) {
        int c = nt*8 + q*2;
        atomicAdd(&sm_s[c],   sums[nt*2]);
        atomicAdd(&sm_s[c+1], sums[nt*2+1]);
        atomicAdd(&sm_q[c],   sumq[nt*2]);
        atomicAdd(&sm_q[c+1], sumq[nt*2+1]);
    }
    __syncthreads();
    if (t < 64) {
        atomicAdd(&g_sum2[t],   sm_s[t]);
        atomicAdd(&g_sumsq2[t], sm_q[t]);
    }
}

// ============================================================================
// pooled m = relu(a2*z_sel+c2); z3 = W3@m -> out
__global__ void k_pool3(const float* __restrict__ W3,
                        const float* __restrict__ g2,
                        const float* __restrict__ be2,
                        float* __restrict__ out) {
    __shared__ float ms[64][65];
    __shared__ float W3sT[CC][EE];
    int b = blockIdx.y;
    int n0 = blockIdx.x * 64;
    int t = threadIdx.x;
    for (int i = t; i < CC*EE; i += 256) {
        int o = i >> 6, c = i & 63;
        W3sT[c][o] = W3[i];
    }
    {
        int o = t & 63;
        int ng = t >> 6;
        float m2 = g_sum2[o] * (1.f/CNT1);
        float v2 = fmaxf(g_sumsq2[o] * (1.f/CNT1) - m2*m2, 0.f);
        float a2o = g2[o] * rsqrtf(v2 + EPSV);
        float c2o = be2[o] - a2o * m2;
        const float* zsel = (a2o >= 0.f) ? g_zmax : g_zmin;
        for (int nl = ng; nl < 64; nl += 4) {
            int point = b*NN + n0 + nl;
            float zm = zsel[point*EE + o];
            ms[nl][o] = fmaxf(fmaf(a2o, zm, c2o), 0.f);
        }
    }
    __syncthreads();
    int nl = t & 63;
    int ob = (t >> 6) * 16;
    float acc[16];
    #pragma unroll
    for (int i = 0; i < 16; i++) acc[i] = 0.f;
    #pragma unroll 4
    for (int c = 0; c < CC; c++) {
        float mv = ms[nl][c];
        #pragma unroll
        for (int i = 0; i < 16; i++)
            acc[i] = fmaf(W3sT[c][ob+i], mv, acc[i]);
    }
    #pragma unroll
    for (int i = 0; i < 16; i++)
        out[(b*EE + ob + i)*NN + n0 + nl] = acc[i];
}

// BN3 stats over out
__global__ void k_stats3(const float* __restrict__ out) {
    __shared__ float r1[256], r2[256];
    int p = blockIdx.x;
    int o = p & 63;
    const float* base = out + (size_t)p*NN;
    int t = threadIdx.x;
    float s = 0.f, q = 0.f;
    for (int i = t; i < NN; i += 256) {
        float v = base[i];
        s += v;
        q = fmaf(v, v, q);
    }
    r1[t] = s; r2[t] = q;
    __syncthreads();
    for (int w = 128; w > 0; w >>= 1) {
        if (t < w) { r1[t] += r1[t+w]; r2[t] += r2[t+w]; }
        __syncthreads();
    }
    if (t == 0) {
        atomicAdd(&g_sum3[o], r1[0]);
        atomicAdd(&g_sumsq3[o], r2[0]);
    }
}

// BN3 + ReLU in place
__global__ void k_out(const float* __restrict__ g3, const float* __restrict__ be3,
                      float* __restrict__ out) {
    __shared__ float sa[EE], sc[EE];
    int t = threadIdx.x;
    if (t < EE) {
        float m3 = g_sum3[t] * (1.f/CNT3);
        float v3 = fmaxf(g_sumsq3[t] * (1.f/CNT3) - m3*m3, 0.f);
        float a3 = g3[t] * rsqrtf(v3 + EPSV);
        sa[t] = a3;
        sc[t] = be3[t] - a3 * m3;
    }
    __syncthreads();
    int gi = blockIdx.x * blockDim.x + t;
    int o = (gi >> 10) & 63;
    float4* out4 = (float4*)out;
    float4 v = out4[gi];
    float a = sa[o], c = sc[o];
    v.x = fmaxf(fmaf(a, v.x, c), 0.f);
    v.y = fmaxf(fmaf(a, v.y, c), 0.f);
    v.z = fmaxf(fmaf(a, v.z, c), 0.f);
    v.w = fmaxf(fmaf(a, v.w, c), 0.f);
    out4[gi] = v;
}

extern "C" void kernel_launch(void* const* d_in, const int* in_sizes, int n_in,
                              void* d_out, int out_size) {
    const float* x   = (const float*)d_in[0];
    const int*   idx = (const int*)  d_in[1];
    const float* W1  = (const float*)d_in[2];
    const float* g1  = (const float*)d_in[4];
    const float* be1 = (const float*)d_in[5];
    const float* W2  = (const float*)d_in[6];
    const float* g2  = (const float*)d_in[8];
    const float* be2 = (const float*)d_in[9];
    const float* W3  = (const float*)d_in[10];
    const float* g3  = (const float*)d_in[12];
    const float* be3 = (const float*)d_in[13];
    float* out = (float*)d_out;

    k_y1    <<<dim3(64, 8), 256>>>(x, W1);
    k_stats1<<<512, 256>>>(idx);
    k_prep  <<<2048, 256>>>(g1, be1);
    k_edge  <<<2048, 128>>>(idx, W2);   // 2048 CTAs x 4 warps x 4 points
    k_pool3 <<<dim3(64, 8), 256>>>(W3, g2, be2, out);
    k_stats3<<<512, 256>>>(out);
    k_out   <<<2048, 256>>>(g3, be3, out);
}

// round 6
// speedup vs baseline: 1.5753x; 1.5753x over previous
#include <cuda_runtime.h>
#include <cuda_bf16.h>
#include <cstdint>

#define BB 8
#define CC 64
#define NN 4096
#define KK 16
#define EE 64
#define NPOINTS (BB*NN)            // 32768
#define CNT1 524288.0f             // B*N*K
#define CNT3 32768.0f              // B*N
#define EPSV 1e-5f

// ---- scratch (device globals: allocation-free rule) ----
__device__ float g_y1t[NPOINTS*EE];       // 8 MB  u = a1 * y after k_prep
__device__ float g_un[NPOINTS*EE];        // 8 MB  un' = u - c1
__device__ float g_zmax[NPOINTS*EE];      // 8 MB
__device__ float g_zmin[NPOINTS*EE];      // 8 MB
__device__ float g_sum1[EE], g_sumsq1[EE];
__device__ float g_sum2[EE], g_sumsq2[EE];
__device__ float g_sum3[EE], g_sumsq3[EE];

// pack two fp32 into bf16x2 (first arg -> low half)
__device__ __forceinline__ uint32_t pack_bf2(float lo_e, float hi_e) {
    uint32_t r;
    asm("cvt.rn.bf16x2.f32 %0, %1, %2;" : "=r"(r) : "f"(hi_e), "f"(lo_e));
    return r;
}

__device__ __forceinline__ void mma16816(float d[4], const uint32_t a[4], uint32_t b0, uint32_t b1) {
    asm volatile(
        "mma.sync.aligned.m16n8k16.row.col.f32.bf16.bf16.f32 "
        "{%0,%1,%2,%3}, {%4,%5,%6,%7}, {%8,%9}, {%0,%1,%2,%3};"
        : "+f"(d[0]), "+f"(d[1]), "+f"(d[2]), "+f"(d[3])
        : "r"(a[0]), "r"(a[1]), "r"(a[2]), "r"(a[3]), "r"(b0), "r"(b1));
}

// split a packed pair (x,y) into hi (bf16) and lo (residual bf16)
__device__ __forceinline__ void split2(float x, float y, uint32_t& hi, uint32_t& lo) {
    hi = pack_bf2(x, y);
    float e0 = __uint_as_float(hi << 16);
    float e1 = __uint_as_float(hi & 0xffff0000u);
    lo = pack_bf2(x - e0, y - e1);
}

// ============================================================================
// y1t[b][n][e] = sum_c W1[e][c] * x[b][c][n];  block(0,0) zeroes accumulators
__global__ void k_y1(const float* __restrict__ x, const float* __restrict__ W1) {
    __shared__ float xs[CC][64];
    __shared__ float W1sT[CC][EE];
    int b = blockIdx.y;
    int n0 = blockIdx.x * 64;
    int t = threadIdx.x;
    if (blockIdx.x == 0 && blockIdx.y == 0 && t < EE) {
        g_sum1[t]=0.f; g_sumsq1[t]=0.f;
        g_sum2[t]=0.f; g_sumsq2[t]=0.f;
        g_sum3[t]=0.f; g_sumsq3[t]=0.f;
    }
    for (int i = t; i < CC*EE; i += 256) {
        int o = i >> 6, c = i & 63;
        W1sT[c][o] = W1[i];
    }
    for (int i = t; i < CC*64; i += 256) {
        int c = i >> 6, j = i & 63;
        xs[c][j] = x[(b*CC + c)*NN + n0 + j];
    }
    __syncthreads();
    int e = t & 63;
    int nb = (t >> 6) * 16;
    float acc[16];
    #pragma unroll
    for (int i = 0; i < 16; i++) acc[i] = 0.f;
    #pragma unroll 4
    for (int c = 0; c < CC; c++) {
        float w = W1sT[c][e];
        #pragma unroll
        for (int i = 0; i < 16; i++) acc[i] = fmaf(w, xs[c][nb+i], acc[i]);
    }
    #pragma unroll
    for (int i = 0; i < 16; i++)
        g_y1t[(b*NN + n0 + nb + i)*EE + e] = acc[i];
}

// BN1 stats over d = y_j - y_n
__global__ void k_stats1(const int* __restrict__ idx) {
    __shared__ float red[4][64];
    int t = threadIdx.x;
    int c = t & 63, g = t >> 6;
    float s = 0.f, q = 0.f;
    int p0 = blockIdx.x * 64;
    for (int pl = g; pl < 64; pl += 4) {
        int point = p0 + pl;
        int brow = (point >> 12) << 12;
        float yn = g_y1t[point*EE + c];
        const int* ip = idx + point*KK;
        #pragma unroll
        for (int k = 0; k < KK; k++) {
            int j = ip[k];
            float yj = g_y1t[(brow + j)*EE + c];
            float d = yj - yn;
            s += d;
            q = fmaf(d, d, q);
        }
    }
    red[g][c] = s;
    __syncthreads();
    if (g == 0) atomicAdd(&g_sum1[c], red[0][c]+red[1][c]+red[2][c]+red[3][c]);
    __syncthreads();
    red[g][c] = q;
    __syncthreads();
    if (g == 0) atomicAdd(&g_sumsq1[c], red[0][c]+red[1][c]+red[2][c]+red[3][c]);
}

// fold BN1 into y: u = a1*y (in place), un' = u - c1
__global__ void k_prep(const float* __restrict__ g1, const float* __restrict__ be1) {
    int i = blockIdx.x * blockDim.x + threadIdx.x;   // float4 index, 524288 total
    int c0 = (i & 15) * 4;
    float a[4], cv[4];
    #pragma unroll
    for (int j = 0; j < 4; j++) {
        int c = c0 + j;
        float m1 = g_sum1[c] * (1.f/CNT1);
        float v1 = fmaxf(g_sumsq1[c] * (1.f/CNT1) - m1*m1, 0.f);
        a[j] = g1[c] * rsqrtf(v1 + EPSV);
        cv[j] = be1[c] - a[j] * m1;
    }
    float4* Y = (float4*)g_y1t;
    float4* U = (float4*)g_un;
    float4 v = Y[i];
    v.x *= a[0]; v.y *= a[1]; v.z *= a[2]; v.w *= a[3];
    Y[i] = v;
    float4 u;
    u.x = v.x - cv[0]; u.y = v.y - cv[1]; u.z = v.z - cv[2]; u.w = v.w - cv[3];
    U[i] = u;
}

// ============================================================================
// Main pass via mma.sync bf16 (split-bf16, 3 terms).
// 2 warps per point, 4 n-tiles each; B fragments live in smem.
__global__ void __launch_bounds__(128, 5) k_edge(const int* __restrict__ idx,
                                                 const float* __restrict__ W2) {
    __shared__ uint4 sB[4][8][32];    // [ks][nt][lane] = (hi0, hi1, lo0, lo1)
    __shared__ float sm_s[64], sm_q[64];
    int t = threadIdx.x;
    int lane = t & 31, w = t >> 5;
    int g = lane >> 2, q = lane & 3;

    // build B fragments once per CTA (warp w handles nt = w, w+4)
    #pragma unroll
    for (int nth = 0; nth < 2; nth++) {
        int nt = w + nth*4;
        int n = nt*8 + g;
        #pragma unroll
        for (int ks = 0; ks < 4; ks++) {
            const float2* wp = (const float2*)(W2 + n*64 + ks*16 + q*2);
            float2 w0 = wp[0];     // rows k, k+1
            float2 w1 = wp[4];     // rows k+8, k+9
            uint32_t h0, l0, h1, l1;
            split2(w0.x, w0.y, h0, l0);
            split2(w1.x, w1.y, h1, l1);
            sB[ks][nt][lane] = make_uint4(h0, h1, l0, l1);
        }
    }
    if (t < 64) { sm_s[t] = 0.f; sm_q[t] = 0.f; }
    __syncthreads();

    int nt0 = (w & 1) * 4;            // this warp's n-tile half
    int pslot = w >> 1;               // 0..1
    float sums[8], sumq[8];
    #pragma unroll
    for (int i = 0; i < 8; i++) { sums[i] = 0.f; sumq[i] = 0.f; }

    #pragma unroll 1
    for (int pi = 0; pi < 8; pi++) {
        int p = blockIdx.x * 16 + pslot * 8 + pi;
        int base = (p >> 12) << 12;
        int j0 = idx[p*KK + g];
        int j1 = idx[p*KK + 8 + g];
        const float* un = g_un  + (size_t)p * EE;
        const float* u0 = g_y1t + (size_t)(base + j0) * EE;
        const float* u1 = g_y1t + (size_t)(base + j1) * EE;

        // A fragments for all 4 k-steps (batched gather for MLP)
        uint32_t Ahi[4][4], Alo[4][4];
        #pragma unroll
        for (int ks = 0; ks < 4; ks++) {
            int c0 = ks*16 + q*2;
            float2 n0  = *(const float2*)(un + c0);
            float2 n1  = *(const float2*)(un + c0 + 8);
            float2 x00 = *(const float2*)(u0 + c0);
            float2 x01 = *(const float2*)(u0 + c0 + 8);
            float2 x10 = *(const float2*)(u1 + c0);
            float2 x11 = *(const float2*)(u1 + c0 + 8);
            float h00 = fmaxf(x00.x - n0.x, 0.f), h01 = fmaxf(x00.y - n0.y, 0.f);
            float h10 = fmaxf(x10.x - n0.x, 0.f), h11 = fmaxf(x10.y - n0.y, 0.f);
            float h02 = fmaxf(x01.x - n1.x, 0.f), h03 = fmaxf(x01.y - n1.y, 0.f);
            float h12 = fmaxf(x11.x - n1.x, 0.f), h13 = fmaxf(x11.y - n1.y, 0.f);
            split2(h00, h01, Ahi[ks][0], Alo[ks][0]);
            split2(h10, h11, Ahi[ks][1], Alo[ks][1]);
            split2(h02, h03, Ahi[ks][2], Alo[ks][2]);
            split2(h12, h13, Ahi[ks][3], Alo[ks][3]);
        }

        float D[4][4];
        #pragma unroll
        for (int j = 0; j < 4; j++)
            #pragma unroll
            for (int i = 0; i < 4; i++) D[j][i] = 0.f;

        #pragma unroll
        for (int ks = 0; ks < 4; ks++) {
            #pragma unroll
            for (int j = 0; j < 4; j++) {
                uint4 bb = sB[ks][nt0 + j][lane];
                mma16816(D[j], Ahi[ks], bb.x, bb.y);
                mma16816(D[j], Alo[ks], bb.x, bb.y);
                mma16816(D[j], Ahi[ks], bb.z, bb.w);
            }
        }

        // reduce over the 16 neighbors (rows)
        #pragma unroll
        for (int j = 0; j < 4; j++) {
            int nt = nt0 + j;
            float d0 = D[j][0], d1 = D[j][1], d2 = D[j][2], d3 = D[j][3];
            sums[j*2]   += d0 + d2;
            sums[j*2+1] += d1 + d3;
            sumq[j*2]   = fmaf(d0, d0, fmaf(d2, d2, sumq[j*2]));
            sumq[j*2+1] = fmaf(d1, d1, fmaf(d3, d3, sumq[j*2+1]));
            float mx0 = fmaxf(d0, d2), mn0 = fminf(d0, d2);
            float mx1 = fmaxf(d1, d3), mn1 = fminf(d1, d3);
            #pragma unroll
            for (int off = 4; off < 32; off <<= 1) {
                mx0 = fmaxf(mx0, __shfl_xor_sync(0xffffffffu, mx0, off));
                mn0 = fminf(mn0, __shfl_xor_sync(0xffffffffu, mn0, off));
                mx1 = fmaxf(mx1, __shfl_xor_sync(0xffffffffu, mx1, off));
                mn1 = fminf(mn1, __shfl_xor_sync(0xffffffffu, mn1, off));
            }
            if (g == 0) {
                size_t o = (size_t)p*EE + nt*8 + q*2;
                *(float2*)(g_zmax + o) = make_float2(mx0, mx1);
                *(float2*)(g_zmin + o) = make_float2(mn0, mn1);
            }
        }
    }

    // BN2 partial sums: smem reduce, then one global atomic per channel
    #pragma unroll
    for (int j = 0; j < 4; j++) {
        int c = (nt0 + j)*8 + q*2;
        atomicAdd(&sm_s[c],   sums[j*2]);
        atomicAdd(&sm_s[c+1], sums[j*2+1]);
        atomicAdd(&sm_q[c],   sumq[j*2]);
        atomicAdd(&sm_q[c+1], sumq[j*2+1]);
    }
    __syncthreads();
    if (t < 64) {
        atomicAdd(&g_sum2[t],   sm_s[t]);
        atomicAdd(&g_sumsq2[t], sm_q[t]);
    }
}

// ============================================================================
// pooled m = relu(a2*z_sel+c2); z3 = W3@m -> out
__global__ void k_pool3(const float* __restrict__ W3,
                        const float* __restrict__ g2,
                        const float* __restrict__ be2,
                        float* __restrict__ out) {
    __shared__ float ms[64][65];
    __shared__ float W3sT[CC][EE];
    int b = blockIdx.y;
    int n0 = blockIdx.x * 64;
    int t = threadIdx.x;
    for (int i = t; i < CC*EE; i += 256) {
        int o = i >> 6, c = i & 63;
        W3sT[c][o] = W3[i];
    }
    {
        int o = t & 63;
        int ng = t >> 6;
        float m2 = g_sum2[o] * (1.f/CNT1);
        float v2 = fmaxf(g_sumsq2[o] * (1.f/CNT1) - m2*m2, 0.f);
        float a2o = g2[o] * rsqrtf(v2 + EPSV);
        float c2o = be2[o] - a2o * m2;
        const float* zsel = (a2o >= 0.f) ? g_zmax : g_zmin;
        for (int nl = ng; nl < 64; nl += 4) {
            int point = b*NN + n0 + nl;
            float zm = zsel[point*EE + o];
            ms[nl][o] = fmaxf(fmaf(a2o, zm, c2o), 0.f);
        }
    }
    __syncthreads();
    int nl = t & 63;
    int ob = (t >> 6) * 16;
    float acc[16];
    #pragma unroll
    for (int i = 0; i < 16; i++) acc[i] = 0.f;
    #pragma unroll 4
    for (int c = 0; c < CC; c++) {
        float mv = ms[nl][c];
        #pragma unroll
        for (int i = 0; i < 16; i++)
            acc[i] = fmaf(W3sT[c][ob+i], mv, acc[i]);
    }
    #pragma unroll
    for (int i = 0; i < 16; i++)
        out[(b*EE + ob + i)*NN + n0 + nl] = acc[i];
}

// BN3 stats over out
__global__ void k_stats3(const float* __restrict__ out) {
    __shared__ float r1[256], r2[256];
    int p = blockIdx.x;
    int o = p & 63;
    const float* base = out + (size_t)p*NN;
    int t = threadIdx.x;
    float s = 0.f, q = 0.f;
    for (int i = t; i < NN; i += 256) {
        float v = base[i];
        s += v;
        q = fmaf(v, v, q);
    }
    r1[t] = s; r2[t] = q;
    __syncthreads();
    for (int w = 128; w > 0; w >>= 1) {
        if (t < w) { r1[t] += r1[t+w]; r2[t] += r2[t+w]; }
        __syncthreads();
    }
    if (t == 0) {
        atomicAdd(&g_sum3[o], r1[0]);
        atomicAdd(&g_sumsq3[o], r2[0]);
    }
}

// BN3 + ReLU in place
__global__ void k_out(const float* __restrict__ g3, const float* __restrict__ be3,
                      float* __restrict__ out) {
    __shared__ float sa[EE], sc[EE];
    int t = threadIdx.x;
    if (t < EE) {
        float m3 = g_sum3[t] * (1.f/CNT3);
        float v3 = fmaxf(g_sumsq3[t] * (1.f/CNT3) - m3*m3, 0.f);
        float a3 = g3[t] * rsqrtf(v3 + EPSV);
        sa[t] = a3;
        sc[t] = be3[t] - a3 * m3;
    }
    __syncthreads();
    int gi = blockIdx.x * blockDim.x + t;
    int o = (gi >> 10) & 63;
    float4* out4 = (float4*)out;
    float4 v = out4[gi];
    float a = sa[o], c = sc[o];
    v.x = fmaxf(fmaf(a, v.x, c), 0.f);
    v.y = fmaxf(fmaf(a, v.y, c), 0.f);
    v.z = fmaxf(fmaf(a, v.z, c), 0.f);
    v.w = fmaxf(fmaf(a, v.w, c), 0.f);
    out4[gi] = v;
}

extern "C" void kernel_launch(void* const* d_in, const int* in_sizes, int n_in,
                              void* d_out, int out_size) {
    const float* x   = (const float*)d_in[0];
    const int*   idx = (const int*)  d_in[1];
    const float* W1  = (const float*)d_in[2];
    const float* g1  = (const float*)d_in[4];
    const float* be1 = (const float*)d_in[5];
    const float* W2  = (const float*)d_in[6];
    const float* g2  = (const float*)d_in[8];
    const float* be2 = (const float*)d_in[9];
    const float* W3  = (const float*)d_in[10];
    const float* g3  = (const float*)d_in[12];
    const float* be3 = (const float*)d_in[13];
    float* out = (float*)d_out;

    k_y1    <<<dim3(64, 8), 256>>>(x, W1);
    k_stats1<<<512, 256>>>(idx);
    k_prep  <<<2048, 256>>>(g1, be1);
    k_edge  <<<2048, 128>>>(idx, W2);   // 16 points per CTA, 2 warps per point
    k_pool3 <<<dim3(64, 8), 256>>>(W3, g2, be2, out);
    k_stats3<<<512, 256>>>(out);
    k_out   <<<2048, 256>>>(g3, be3, out);
}

// round 7
// speedup vs baseline: 1.7921x; 1.1376x over previous
#include <cuda_runtime.h>
#include <cuda_bf16.h>
#include <cstdint>

#define BB 8
#define CC 64
#define NN 4096
#define KK 16
#define EE 64
#define NPOINTS (BB*NN)            // 32768
#define CNT1 524288.0f             // B*N*K
#define CNT3 32768.0f              // B*N
#define EPSV 1e-5f

// ---- scratch (device globals: allocation-free rule) ----
__device__ float g_y1t[NPOINTS*EE];       // 8 MB  raw y1 transposed [point][c]
__device__ float g_u[NPOINTS*EE];         // 8 MB  permuted u = a1*y
__device__ float g_un[NPOINTS*EE];        // 8 MB  permuted un' = u - c1
__device__ float g_zmax[NPOINTS*EE];      // 8 MB
__device__ float g_zmin[NPOINTS*EE];      // 8 MB
__device__ float g_sum1[EE], g_sumsq1[EE];
__device__ float g_sum2[EE], g_sumsq2[EE];
__device__ float g_sum3[EE], g_sumsq3[EE];

// pack two fp32 into bf16x2 (first arg -> low half)
__device__ __forceinline__ uint32_t pack_bf2(float lo_e, float hi_e) {
    uint32_t r;
    asm("cvt.rn.bf16x2.f32 %0, %1, %2;" : "=r"(r) : "f"(hi_e), "f"(lo_e));
    return r;
}

__device__ __forceinline__ void mma16816(float d[4], const uint32_t a[4], uint32_t b0, uint32_t b1) {
    asm volatile(
        "mma.sync.aligned.m16n8k16.row.col.f32.bf16.bf16.f32 "
        "{%0,%1,%2,%3}, {%4,%5,%6,%7}, {%8,%9}, {%0,%1,%2,%3};"
        : "+f"(d[0]), "+f"(d[1]), "+f"(d[2]), "+f"(d[3])
        : "r"(a[0]), "r"(a[1]), "r"(a[2]), "r"(a[3]), "r"(b0), "r"(b1));
}

// split a packed pair (x,y) into hi (bf16) and lo (residual bf16)
__device__ __forceinline__ void split2(float x, float y, uint32_t& hi, uint32_t& lo) {
    hi = pack_bf2(x, y);
    float e0 = __uint_as_float(hi << 16);
    float e1 = __uint_as_float(hi & 0xffff0000u);
    lo = pack_bf2(x - e0, y - e1);
}

// ============================================================================
// y1t[b][n][e] = sum_c W1[e][c] * x[b][c][n];  block(0,0) zeroes accumulators
__global__ void k_y1(const float* __restrict__ x, const float* __restrict__ W1) {
    __shared__ float xs[CC][64];
    __shared__ float W1sT[CC][EE];
    int b = blockIdx.y;
    int n0 = blockIdx.x * 64;
    int t = threadIdx.x;
    if (blockIdx.x == 0 && blockIdx.y == 0 && t < EE) {
        g_sum1[t]=0.f; g_sumsq1[t]=0.f;
        g_sum2[t]=0.f; g_sumsq2[t]=0.f;
        g_sum3[t]=0.f; g_sumsq3[t]=0.f;
    }
    for (int i = t; i < CC*EE; i += 256) {
        int o = i >> 6, c = i & 63;
        W1sT[c][o] = W1[i];
    }
    for (int i = t; i < CC*64; i += 256) {
        int c = i >> 6, j = i & 63;
        xs[c][j] = x[(b*CC + c)*NN + n0 + j];
    }
    __syncthreads();
    int e = t & 63;
    int nb = (t >> 6) * 16;
    float acc[16];
    #pragma unroll
    for (int i = 0; i < 16; i++) acc[i] = 0.f;
    #pragma unroll 4
    for (int c = 0; c < CC; c++) {
        float w = W1sT[c][e];
        #pragma unroll
        for (int i = 0; i < 16; i++) acc[i] = fmaf(w, xs[c][nb+i], acc[i]);
    }
    #pragma unroll
    for (int i = 0; i < 16; i++)
        g_y1t[(b*NN + n0 + nb + i)*EE + e] = acc[i];
}

// BN1 stats over d = y_j - y_n (float4 gathers, idx shared via shfl)
__global__ void k_stats1(const int* __restrict__ idx) {
    __shared__ float4 red_s[16][16];
    __shared__ float4 red_q[16][16];
    int t = threadIdx.x;
    int c4 = t & 15, g = t >> 4;       // 16 groups of 16 threads (half-warps)
    float4 s = make_float4(0.f,0.f,0.f,0.f);
    float4 q = make_float4(0.f,0.f,0.f,0.f);
    int p0 = blockIdx.x * 64;
    #pragma unroll 1
    for (int pl = 0; pl < 4; pl++) {
        int point = p0 + g*4 + pl;
        int brow = point & ~(NN-1);
        int jown = idx[point*KK + c4];   // lane c4 holds neighbor k=c4
        float4 yn = *(const float4*)(g_y1t + (size_t)point*EE + c4*4);
        #pragma unroll
        for (int k = 0; k < KK; k++) {
            int j = __shfl_sync(0xffffffffu, jown, ((t & 31) & 16) | k, 32);
            float4 yj = *(const float4*)(g_y1t + (size_t)(brow + j)*EE + c4*4);
            float dx = yj.x - yn.x, dy = yj.y - yn.y, dz = yj.z - yn.z, dw = yj.w - yn.w;
            s.x += dx; s.y += dy; s.z += dz; s.w += dw;
            q.x = fmaf(dx, dx, q.x); q.y = fmaf(dy, dy, q.y);
            q.z = fmaf(dz, dz, q.z); q.w = fmaf(dw, dw, q.w);
        }
    }
    red_s[g][c4] = s;
    red_q[g][c4] = q;
    __syncthreads();
    if (t < 64) {
        float ss = 0.f, qq = 0.f;
        #pragma unroll
        for (int gg = 0; gg < 16; gg++) {
            ss += ((const float*)&red_s[gg][t >> 2])[t & 3];
            qq += ((const float*)&red_q[gg][t >> 2])[t & 3];
        }
        atomicAdd(&g_sum1[t], ss);
        atomicAdd(&g_sumsq1[t], qq);
    }
}

// fold BN1 into y with CHANNEL PERMUTATION:
// phys float4 slot (blk, q) holds orig channels {blk*16+2q, +1, blk*16+2q+8, +9}
// so each MMA lane's A-fragment pair-of-pairs is one contiguous float4.
__global__ void k_prep(const float* __restrict__ g1, const float* __restrict__ be1) {
    int i = blockIdx.x * blockDim.x + threadIdx.x;   // phys float4 id, 524288 total
    int point = i >> 4;
    int blk = (i >> 2) & 3;
    int q = i & 3;
    int cb = blk*16 + q*2;
    int co[4] = {cb, cb+1, cb+8, cb+9};
    float a[4], cv[4];
    #pragma unroll
    for (int j = 0; j < 4; j++) {
        int c = co[j];
        float m1 = g_sum1[c] * (1.f/CNT1);
        float v1 = fmaxf(g_sumsq1[c] * (1.f/CNT1) - m1*m1, 0.f);
        a[j] = g1[c] * rsqrtf(v1 + EPSV);
        cv[j] = be1[c] - a[j] * m1;
    }
    const float* yrow = g_y1t + (size_t)point*EE + blk*16;
    float2 A = *(const float2*)(yrow + q*2);
    float2 B = *(const float2*)(yrow + q*2 + 8);
    float4 u;
    u.x = A.x*a[0]; u.y = A.y*a[1]; u.z = B.x*a[2]; u.w = B.y*a[3];
    float4 un;
    un.x = u.x - cv[0]; un.y = u.y - cv[1]; un.z = u.z - cv[2]; un.w = u.w - cv[3];
    ((float4*)g_u)[i]  = u;
    ((float4*)g_un)[i] = un;
}

// ============================================================================
// Main pass via mma.sync bf16 (split-bf16, 3 terms).
// 2 warps per point, 4 n-tiles each; B fragments in smem; float4 gathers.
__global__ void __launch_bounds__(128, 5) k_edge(const int* __restrict__ idx,
                                                 const float* __restrict__ W2) {
    __shared__ uint4 sB[4][8][32];    // [ks][nt][lane] = (hi0, hi1, lo0, lo1)
    __shared__ float sm_s[64], sm_q[64];
    int t = threadIdx.x;
    int lane = t & 31, w = t >> 5;
    int g = lane >> 2, q = lane & 3;

    // build B fragments once per CTA (warp w handles nt = w, w+4)
    #pragma unroll
    for (int nth = 0; nth < 2; nth++) {
        int nt = w + nth*4;
        int n = nt*8 + g;
        #pragma unroll
        for (int ks = 0; ks < 4; ks++) {
            const float2* wp = (const float2*)(W2 + n*64 + ks*16 + q*2);
            float2 w0 = wp[0];     // rows k, k+1
            float2 w1 = wp[4];     // rows k+8, k+9
            uint32_t h0, l0, h1, l1;
            split2(w0.x, w0.y, h0, l0);
            split2(w1.x, w1.y, h1, l1);
            sB[ks][nt][lane] = make_uint4(h0, h1, l0, l1);
        }
    }
    if (t < 64) { sm_s[t] = 0.f; sm_q[t] = 0.f; }
    __syncthreads();

    int nt0 = (w & 1) * 4;            // this warp's n-tile half
    int pslot = w >> 1;               // 0..1
    float sums[8], sumq[8];
    #pragma unroll
    for (int i = 0; i < 8; i++) { sums[i] = 0.f; sumq[i] = 0.f; }

    #pragma unroll 1
    for (int pi = 0; pi < 8; pi++) {
        int p = blockIdx.x * 16 + pslot * 8 + pi;
        int base = p & ~(NN-1);
        int j0 = idx[p*KK + g];
        int j1 = idx[p*KK + 8 + g];
        const float4* unr = (const float4*)(g_un + (size_t)p * EE);
        const float4* u0  = (const float4*)(g_u  + (size_t)(base + j0) * EE);
        const float4* u1  = (const float4*)(g_u  + (size_t)(base + j1) * EE);

        // A fragments for all 4 k-steps: one float4 per stream per ks
        uint32_t Ahi[4][4], Alo[4][4];
        #pragma unroll
        for (int ks = 0; ks < 4; ks++) {
            float4 nf = unr[ks*4 + q];
            float4 x0 = u0[ks*4 + q];
            float4 x1 = u1[ks*4 + q];
            float h00 = fmaxf(x0.x - nf.x, 0.f), h01 = fmaxf(x0.y - nf.y, 0.f);
            float h02 = fmaxf(x0.z - nf.z, 0.f), h03 = fmaxf(x0.w - nf.w, 0.f);
            float h10 = fmaxf(x1.x - nf.x, 0.f), h11 = fmaxf(x1.y - nf.y, 0.f);
            float h12 = fmaxf(x1.z - nf.z, 0.f), h13 = fmaxf(x1.w - nf.w, 0.f);
            split2(h00, h01, Ahi[ks][0], Alo[ks][0]);   // row g,   frag cols 2q,2q+1
            split2(h10, h11, Ahi[ks][1], Alo[ks][1]);   // row g+8, frag cols 2q,2q+1
            split2(h02, h03, Ahi[ks][2], Alo[ks][2]);   // row g,   frag cols 2q+8,2q+9
            split2(h12, h13, Ahi[ks][3], Alo[ks][3]);   // row g+8, frag cols 2q+8,2q+9
        }

        float D[4][4];
        #pragma unroll
        for (int j = 0; j < 4; j++)
            #pragma unroll
            for (int i = 0; i < 4; i++) D[j][i] = 0.f;

        #pragma unroll
        for (int ks = 0; ks < 4; ks++) {
            #pragma unroll
            for (int j = 0; j < 4; j++) {
                uint4 bb = sB[ks][nt0 + j][lane];
                mma16816(D[j], Ahi[ks], bb.x, bb.y);
                mma16816(D[j], Alo[ks], bb.x, bb.y);
                mma16816(D[j], Ahi[ks], bb.z, bb.w);
            }
        }

        // reduce over the 16 neighbors (rows)
        #pragma unroll
        for (int j = 0; j < 4; j++) {
            int nt = nt0 + j;
            float d0 = D[j][0], d1 = D[j][1], d2 = D[j][2], d3 = D[j][3];
            sums[j*2]   += d0 + d2;
            sums[j*2+1] += d1 + d3;
            sumq[j*2]   = fmaf(d0, d0, fmaf(d2, d2, sumq[j*2]));
            sumq[j*2+1] = fmaf(d1, d1, fmaf(d3, d3, sumq[j*2+1]));
            float mx0 = fmaxf(d0, d2), mn0 = fminf(d0, d2);
            float mx1 = fmaxf(d1, d3), mn1 = fminf(d1, d3);
            #pragma unroll
            for (int off = 4; off < 32; off <<= 1) {
                mx0 = fmaxf(mx0, __shfl_xor_sync(0xffffffffu, mx0, off));
                mn0 = fminf(mn0, __shfl_xor_sync(0xffffffffu, mn0, off));
                mx1 = fmaxf(mx1, __shfl_xor_sync(0xffffffffu, mx1, off));
                mn1 = fminf(mn1, __shfl_xor_sync(0xffffffffu, mn1, off));
            }
            if (g == 0) {
                size_t o = (size_t)p*EE + nt*8 + q*2;
                *(float2*)(g_zmax + o) = make_float2(mx0, mx1);
                *(float2*)(g_zmin + o) = make_float2(mn0, mn1);
            }
        }
    }

    // BN2 partial sums: smem reduce, then one global atomic per channel
    #pragma unroll
    for (int j = 0; j < 4; j++) {
        int c = (nt0 + j)*8 + q*2;
        atomicAdd(&sm_s[c],   sums[j*2]);
        atomicAdd(&sm_s[c+1], sums[j*2+1]);
        atomicAdd(&sm_q[c],   sumq[j*2]);
        atomicAdd(&sm_q[c+1], sumq[j*2+1]);
    }
    __syncthreads();
    if (t < 64) {
        atomicAdd(&g_sum2[t],   sm_s[t]);
        atomicAdd(&g_sumsq2[t], sm_q[t]);
    }
}

// ============================================================================
// pooled m = relu(a2*z_sel+c2); z3 = W3@m -> out
__global__ void k_pool3(const float* __restrict__ W3,
                        const float* __restrict__ g2,
                        const float* __restrict__ be2,
                        float* __restrict__ out) {
    __shared__ float ms[64][65];
    __shared__ float W3sT[CC][EE];
    int b = blockIdx.y;
    int n0 = blockIdx.x * 64;
    int t = threadIdx.x;
    for (int i = t; i < CC*EE; i += 256) {
        int o = i >> 6, c = i & 63;
        W3sT[c][o] = W3[i];
    }
    {
        int o = t & 63;
        int ng = t >> 6;
        float m2 = g_sum2[o] * (1.f/CNT1);
        float v2 = fmaxf(g_sumsq2[o] * (1.f/CNT1) - m2*m2, 0.f);
        float a2o = g2[o] * rsqrtf(v2 + EPSV);
        float c2o = be2[o] - a2o * m2;
        const float* zsel = (a2o >= 0.f) ? g_zmax : g_zmin;
        for (int nl = ng; nl < 64; nl += 4) {
            int point = b*NN + n0 + nl;
            float zm = zsel[point*EE + o];
            ms[nl][o] = fmaxf(fmaf(a2o, zm, c2o), 0.f);
        }
    }
    __syncthreads();
    int nl = t & 63;
    int ob = (t >> 6) * 16;
    float acc[16];
    #pragma unroll
    for (int i = 0; i < 16; i++) acc[i] = 0.f;
    #pragma unroll 4
    for (int c = 0; c < CC; c++) {
        float mv = ms[nl][c];
        #pragma unroll
        for (int i = 0; i < 16; i++)
            acc[i] = fmaf(W3sT[c][ob+i], mv, acc[i]);
    }
    #pragma unroll
    for (int i = 0; i < 16; i++)
        out[(b*EE + ob + i)*NN + n0 + nl] = acc[i];
}

// BN3 stats over out
__global__ void k_stats3(const float* __restrict__ out) {
    __shared__ float r1[256], r2[256];
    int p = blockIdx.x;
    int o = p & 63;
    const float* base = out + (size_t)p*NN;
    int t = threadIdx.x;
    float s = 0.f, q = 0.f;
    for (int i = t; i < NN; i += 256) {
        float v = base[i];
        s += v;
        q = fmaf(v, v, q);
    }
    r1[t] = s; r2[t] = q;
    __syncthreads();
    for (int w = 128; w > 0; w >>= 1) {
        if (t < w) { r1[t] += r1[t+w]; r2[t] += r2[t+w]; }
        __syncthreads();
    }
    if (t == 0) {
        atomicAdd(&g_sum3[o], r1[0]);
        atomicAdd(&g_sumsq3[o], r2[0]);
    }
}

// BN3 + ReLU in place
__global__ void k_out(const float* __restrict__ g3, const float* __restrict__ be3,
                      float* __restrict__ out) {
    __shared__ float sa[EE], sc[EE];
    int t = threadIdx.x;
    if (t < EE) {
        float m3 = g_sum3[t] * (1.f/CNT3);
        float v3 = fmaxf(g_sumsq3[t] * (1.f/CNT3) - m3*m3, 0.f);
        float a3 = g3[t] * rsqrtf(v3 + EPSV);
        sa[t] = a3;
        sc[t] = be3[t] - a3 * m3;
    }
    __syncthreads();
    int gi = blockIdx.x * blockDim.x + t;
    int o = (gi >> 10) & 63;
    float4* out4 = (float4*)out;
    float4 v = out4[gi];
    float a = sa[o], c = sc[o];
    v.x = fmaxf(fmaf(a, v.x, c), 0.f);
    v.y = fmaxf(fmaf(a, v.y, c), 0.f);
    v.z = fmaxf(fmaf(a, v.z, c), 0.f);
    v.w = fmaxf(fmaf(a, v.w, c), 0.f);
    out4[gi] = v;
}

extern "C" void kernel_launch(void* const* d_in, const int* in_sizes, int n_in,
                              void* d_out, int out_size) {
    const float* x   = (const float*)d_in[0];
    const int*   idx = (const int*)  d_in[1];
    const float* W1  = (const float*)d_in[2];
    const float* g1  = (const float*)d_in[4];
    const float* be1 = (const float*)d_in[5];
    const float* W2  = (const float*)d_in[6];
    const float* g2  = (const float*)d_in[8];
    const float* be2 = (const float*)d_in[9];
    const float* W3  = (const float*)d_in[10];
    const float* g3  = (const float*)d_in[12];
    const float* be3 = (const float*)d_in[13];
    float* out = (float*)d_out;

    k_y1    <<<dim3(64, 8), 256>>>(x, W1);
    k_stats1<<<512, 256>>>(idx);
    k_prep  <<<2048, 256>>>(g1, be1);
    k_edge  <<<2048, 128>>>(idx, W2);   // 16 points per CTA, 2 warps per point
    k_pool3 <<<dim3(64, 8), 256>>>(W3, g2, be2, out);
    k_stats3<<<512, 256>>>(out);
    k_out   <<<2048, 256>>>(g3, be3, out);
}

// round 8
// speedup vs baseline: 2.1674x; 1.2094x over previous
#include <cuda_runtime.h>
#include <cuda_bf16.h>
#include <cstdint>

#define BB 8
#define CC 64
#define NN 4096
#define KK 16
#define EE 64
#define NPOINTS (BB*NN)            // 32768
#define CNT1 524288.0f             // B*N*K
#define CNT3 32768.0f              // B*N
#define EPSV 1e-5f

// ---- scratch (device globals: allocation-free rule) ----
__device__ float g_y1t[NPOINTS*EE];       // 8 MB  raw y1 transposed [point][c]
__device__ float g_u[NPOINTS*EE];         // 8 MB  permuted u = a1*y
__device__ float g_un[NPOINTS*EE];        // 8 MB  permuted un' = u - c1
__device__ float g_zmax[NPOINTS*EE];      // 8 MB
__device__ float g_zmin[NPOINTS*EE];      // 8 MB
__device__ float g_sum1[EE], g_sumsq1[EE];
__device__ float g_sum2[EE], g_sumsq2[EE];
__device__ float g_sum3[EE], g_sumsq3[EE];

// pack two fp32 into bf16x2 (first arg -> low half)
__device__ __forceinline__ uint32_t pack_bf2(float lo_e, float hi_e) {
    uint32_t r;
    asm("cvt.rn.bf16x2.f32 %0, %1, %2;" : "=r"(r) : "f"(hi_e), "f"(lo_e));
    return r;
}

__device__ __forceinline__ void mma16816(float d[4], const uint32_t a[4], uint32_t b0, uint32_t b1) {
    asm volatile(
        "mma.sync.aligned.m16n8k16.row.col.f32.bf16.bf16.f32 "
        "{%0,%1,%2,%3}, {%4,%5,%6,%7}, {%8,%9}, {%0,%1,%2,%3};"
        : "+f"(d[0]), "+f"(d[1]), "+f"(d[2]), "+f"(d[3])
        : "r"(a[0]), "r"(a[1]), "r"(a[2]), "r"(a[3]), "r"(b0), "r"(b1));
}

// split a packed pair (x,y) into hi (bf16) and lo (residual bf16)
__device__ __forceinline__ void split2(float x, float y, uint32_t& hi, uint32_t& lo) {
    hi = pack_bf2(x, y);
    float e0 = __uint_as_float(hi << 16);
    float e1 = __uint_as_float(hi & 0xffff0000u);
    lo = pack_bf2(x - e0, y - e1);
}

// ============================================================================
// y1t[b][n][e] = sum_c W1[e][c] * x[b][c][n];  block(0,0) zeroes accumulators
__global__ void k_y1(const float* __restrict__ x, const float* __restrict__ W1) {
    __shared__ float xs[CC][64];
    __shared__ float W1sT[CC][EE];
    int b = blockIdx.y;
    int n0 = blockIdx.x * 64;
    int t = threadIdx.x;
    if (blockIdx.x == 0 && blockIdx.y == 0 && t < EE) {
        g_sum1[t]=0.f; g_sumsq1[t]=0.f;
        g_sum2[t]=0.f; g_sumsq2[t]=0.f;
        g_sum3[t]=0.f; g_sumsq3[t]=0.f;
    }
    for (int i = t; i < CC*EE; i += 256) {
        int o = i >> 6, c = i & 63;
        W1sT[c][o] = W1[i];
    }
    for (int i = t; i < CC*64; i += 256) {
        int c = i >> 6, j = i & 63;
        xs[c][j] = x[(b*CC + c)*NN + n0 + j];
    }
    __syncthreads();
    int e = t & 63;
    int nb = (t >> 6) * 16;
    float acc[16];
    #pragma unroll
    for (int i = 0; i < 16; i++) acc[i] = 0.f;
    #pragma unroll 4
    for (int c = 0; c < CC; c++) {
        float w = W1sT[c][e];
        #pragma unroll
        for (int i = 0; i < 16; i++) acc[i] = fmaf(w, xs[c][nb+i], acc[i]);
    }
    #pragma unroll
    for (int i = 0; i < 16; i++)
        g_y1t[(b*NN + n0 + nb + i)*EE + e] = acc[i];
}

// BN1 stats over d = y_j - y_n (float4 gathers, idx shared via shfl)
__global__ void k_stats1(const int* __restrict__ idx) {
    __shared__ float4 red_s[16][16];
    __shared__ float4 red_q[16][16];
    int t = threadIdx.x;
    int c4 = t & 15, g = t >> 4;       // 16 groups of 16 threads (half-warps)
    float4 s = make_float4(0.f,0.f,0.f,0.f);
    float4 q = make_float4(0.f,0.f,0.f,0.f);
    int p0 = blockIdx.x * 64;
    #pragma unroll 1
    for (int pl = 0; pl < 4; pl++) {
        int point = p0 + g*4 + pl;
        int brow = point & ~(NN-1);
        int jown = idx[point*KK + c4];   // lane c4 holds neighbor k=c4
        float4 yn = *(const float4*)(g_y1t + (size_t)point*EE + c4*4);
        #pragma unroll
        for (int k = 0; k < KK; k++) {
            int j = __shfl_sync(0xffffffffu, jown, ((t & 31) & 16) | k, 32);
            float4 yj = *(const float4*)(g_y1t + (size_t)(brow + j)*EE + c4*4);
            float dx = yj.x - yn.x, dy = yj.y - yn.y, dz = yj.z - yn.z, dw = yj.w - yn.w;
            s.x += dx; s.y += dy; s.z += dz; s.w += dw;
            q.x = fmaf(dx, dx, q.x); q.y = fmaf(dy, dy, q.y);
            q.z = fmaf(dz, dz, q.z); q.w = fmaf(dw, dw, q.w);
        }
    }
    red_s[g][c4] = s;
    red_q[g][c4] = q;
    __syncthreads();
    if (t < 64) {
        float ss = 0.f, qq = 0.f;
        #pragma unroll
        for (int gg = 0; gg < 16; gg++) {
            ss += ((const float*)&red_s[gg][t >> 2])[t & 3];
            qq += ((const float*)&red_q[gg][t >> 2])[t & 3];
        }
        atomicAdd(&g_sum1[t], ss);
        atomicAdd(&g_sumsq1[t], qq);
    }
}

// fold BN1 into y with CHANNEL PERMUTATION:
// phys float4 slot (blk, q) holds orig channels {blk*16+2q, +1, blk*16+2q+8, +9}
__global__ void k_prep(const float* __restrict__ g1, const float* __restrict__ be1) {
    int i = blockIdx.x * blockDim.x + threadIdx.x;   // phys float4 id, 524288 total
    int point = i >> 4;
    int blk = (i >> 2) & 3;
    int q = i & 3;
    int cb = blk*16 + q*2;
    int co[4] = {cb, cb+1, cb+8, cb+9};
    float a[4], cv[4];
    #pragma unroll
    for (int j = 0; j < 4; j++) {
        int c = co[j];
        float m1 = g_sum1[c] * (1.f/CNT1);
        float v1 = fmaxf(g_sumsq1[c] * (1.f/CNT1) - m1*m1, 0.f);
        a[j] = g1[c] * rsqrtf(v1 + EPSV);
        cv[j] = be1[c] - a[j] * m1;
    }
    const float* yrow = g_y1t + (size_t)point*EE + blk*16;
    float2 A = *(const float2*)(yrow + q*2);
    float2 B = *(const float2*)(yrow + q*2 + 8);
    float4 u;
    u.x = A.x*a[0]; u.y = A.y*a[1]; u.z = B.x*a[2]; u.w = B.y*a[3];
    float4 un;
    un.x = u.x - cv[0]; un.y = u.y - cv[1]; un.z = u.z - cv[2]; un.w = u.w - cv[3];
    ((float4*)g_u)[i]  = u;
    ((float4*)g_un)[i] = un;
}

// ============================================================================
// Main pass via mma.sync bf16 (split-bf16, 3 terms), OPERAND-SWAPPED:
// A = W2 rows (register-resident), B = gathered H with neighbors as N dim.
// D tile = [16 out-channels x 8 neighbors]. 2 warps per point, 2 m-tiles each.
// Zero shared-memory loads in the point loop.
__global__ void __launch_bounds__(128, 4) k_edge(const int* __restrict__ idx,
                                                 const float* __restrict__ W2) {
    __shared__ float sm_s[64], sm_q[64];
    int t = threadIdx.x;
    int lane = t & 31, w = t >> 5;
    int g = lane >> 2, q = lane & 3;

    if (t < 64) { sm_s[t] = 0.f; sm_q[t] = 0.f; }

    // A = W2 fragments for this warp's 2 m-tiles (32 output channels), resident
    int mtb = (w & 1) * 2;            // m-tile base: 0 or 2
    uint32_t Ahi[2][4][4], Alo[2][4][4];
    #pragma unroll
    for (int mi = 0; mi < 2; mi++) {
        int o0 = (mtb + mi)*16 + g;
        #pragma unroll
        for (int ks = 0; ks < 4; ks++) {
            int cb = ks*16 + q*2;
            const float* r0 = W2 + o0*64 + cb;        // row g
            const float* r1 = W2 + (o0+8)*64 + cb;    // row g+8
            float2 a00 = *(const float2*)(r0);        // cols cb, cb+1
            float2 a01 = *(const float2*)(r0 + 8);    // cols cb+8, cb+9
            float2 a10 = *(const float2*)(r1);
            float2 a11 = *(const float2*)(r1 + 8);
            split2(a00.x, a00.y, Ahi[mi][ks][0], Alo[mi][ks][0]);
            split2(a10.x, a10.y, Ahi[mi][ks][1], Alo[mi][ks][1]);
            split2(a01.x, a01.y, Ahi[mi][ks][2], Alo[mi][ks][2]);
            split2(a11.x, a11.y, Ahi[mi][ks][3], Alo[mi][ks][3]);
        }
    }
    __syncthreads();

    int pslot = w >> 1;               // 0..1
    float sums[4], sumq[4];           // [mi*2 + row(g / g+8)]
    #pragma unroll
    for (int i = 0; i < 4; i++) { sums[i] = 0.f; sumq[i] = 0.f; }

    #pragma unroll 1
    for (int pi = 0; pi < 8; pi++) {
        int p = blockIdx.x * 16 + pslot * 8 + pi;
        int base = p & ~(NN-1);
        int j0 = idx[p*KK + g];          // neighbor column g of n-tile 0
        int j1 = idx[p*KK + 8 + g];      // neighbor column g of n-tile 1
        const float4* unr = (const float4*)(g_un + (size_t)p * EE);
        const float4* u0  = (const float4*)(g_u  + (size_t)(base + j0) * EE);
        const float4* u1  = (const float4*)(g_u  + (size_t)(base + j1) * EE);

        float D[2][2][4];                // [mi][ntile][frag]
        #pragma unroll
        for (int mi = 0; mi < 2; mi++)
            #pragma unroll
            for (int nt = 0; nt < 2; nt++)
                #pragma unroll
                for (int i = 0; i < 4; i++) D[mi][nt][i] = 0.f;

        #pragma unroll
        for (int ks = 0; ks < 4; ks++) {
            float4 nf = unr[ks*4 + q];
            float4 x0 = u0[ks*4 + q];
            float4 x1 = u1[ks*4 + q];
            // B fragments: col g, k-rows {2q,2q+1} (b0) and {2q+8,2q+9} (b1)
            uint32_t bh00, bl00, bh01, bl01;   // ntile 0
            uint32_t bh10, bl10, bh11, bl11;   // ntile 1
            split2(fmaxf(x0.x - nf.x, 0.f), fmaxf(x0.y - nf.y, 0.f), bh00, bl00);
            split2(fmaxf(x0.z - nf.z, 0.f), fmaxf(x0.w - nf.w, 0.f), bh01, bl01);
            split2(fmaxf(x1.x - nf.x, 0.f), fmaxf(x1.y - nf.y, 0.f), bh10, bl10);
            split2(fmaxf(x1.z - nf.z, 0.f), fmaxf(x1.w - nf.w, 0.f), bh11, bl11);
            #pragma unroll
            for (int mi = 0; mi < 2; mi++) {
                mma16816(D[mi][0], Ahi[mi][ks], bh00, bh01);
                mma16816(D[mi][0], Alo[mi][ks], bh00, bh01);
                mma16816(D[mi][0], Ahi[mi][ks], bl00, bl01);
                mma16816(D[mi][1], Ahi[mi][ks], bh10, bh11);
                mma16816(D[mi][1], Alo[mi][ks], bh10, bh11);
                mma16816(D[mi][1], Ahi[mi][ks], bl10, bl11);
            }
        }

        // reduce over neighbors: in-thread (2 cols x 2 ntiles), then shfl over q
        #pragma unroll
        for (int mi = 0; mi < 2; mi++) {
            float d00 = D[mi][0][0], d01 = D[mi][0][1];   // row g, nt0 cols
            float d10 = D[mi][1][0], d11 = D[mi][1][1];   // row g, nt1 cols
            float e00 = D[mi][0][2], e01 = D[mi][0][3];   // row g+8
            float e10 = D[mi][1][2], e11 = D[mi][1][3];
            // BN2 sums (each (k, ch) owned exactly once)
            sums[mi*2]   += (d00 + d01) + (d10 + d11);
            sums[mi*2+1] += (e00 + e01) + (e10 + e11);
            sumq[mi*2]   = fmaf(d00,d00, fmaf(d01,d01, fmaf(d10,d10, fmaf(d11,d11, sumq[mi*2]))));
            sumq[mi*2+1] = fmaf(e00,e00, fmaf(e01,e01, fmaf(e10,e10, fmaf(e11,e11, sumq[mi*2+1]))));
            float mx0 = fmaxf(fmaxf(d00, d01), fmaxf(d10, d11));
            float mn0 = fminf(fminf(d00, d01), fminf(d10, d11));
            float mx1 = fmaxf(fmaxf(e00, e01), fmaxf(e10, e11));
            float mn1 = fminf(fminf(e00, e01), fminf(e10, e11));
            #pragma unroll
            for (int off = 1; off < 4; off <<= 1) {
                mx0 = fmaxf(mx0, __shfl_xor_sync(0xffffffffu, mx0, off));
                mn0 = fminf(mn0, __shfl_xor_sync(0xffffffffu, mn0, off));
                mx1 = fmaxf(mx1, __shfl_xor_sync(0xffffffffu, mx1, off));
                mn1 = fminf(mn1, __shfl_xor_sync(0xffffffffu, mn1, off));
            }
            if (q == 0) {
                int ch = (mtb + mi)*16 + g;
                g_zmax[(size_t)p*EE + ch]     = mx0;
                g_zmax[(size_t)p*EE + ch + 8] = mx1;
                g_zmin[(size_t)p*EE + ch]     = mn0;
                g_zmin[(size_t)p*EE + ch + 8] = mn1;
            }
        }
    }

    // BN2 sums: shfl-reduce over q, stage in smem, one global atomic per channel
    #pragma unroll
    for (int i = 0; i < 4; i++) {
        float s = sums[i], qq = sumq[i];
        #pragma unroll
        for (int off = 1; off < 4; off <<= 1) {
            s  += __shfl_xor_sync(0xffffffffu, s, off);
            qq += __shfl_xor_sync(0xffffffffu, qq, off);
        }
        if (q == 0) {
            int ch = (mtb + (i >> 1))*16 + g + (i & 1)*8;
            atomicAdd(&sm_s[ch], s);
            atomicAdd(&sm_q[ch], qq);
        }
    }
    __syncthreads();
    if (t < 64) {
        atomicAdd(&g_sum2[t],   sm_s[t]);
        atomicAdd(&g_sumsq2[t], sm_q[t]);
    }
}

// ============================================================================
// pooled m = relu(a2*z_sel+c2); z3 = W3@m -> out
__global__ void k_pool3(const float* __restrict__ W3,
                        const float* __restrict__ g2,
                        const float* __restrict__ be2,
                        float* __restrict__ out) {
    __shared__ float ms[64][65];
    __shared__ float W3sT[CC][EE];
    int b = blockIdx.y;
    int n0 = blockIdx.x * 64;
    int t = threadIdx.x;
    for (int i = t; i < CC*EE; i += 256) {
        int o = i >> 6, c = i & 63;
        W3sT[c][o] = W3[i];
    }
    {
        int o = t & 63;
        int ng = t >> 6;
        float m2 = g_sum2[o] * (1.f/CNT1);
        float v2 = fmaxf(g_sumsq2[o] * (1.f/CNT1) - m2*m2, 0.f);
        float a2o = g2[o] * rsqrtf(v2 + EPSV);
        float c2o = be2[o] - a2o * m2;
        const float* zsel = (a2o >= 0.f) ? g_zmax : g_zmin;
        for (int nl = ng; nl < 64; nl += 4) {
            int point = b*NN + n0 + nl;
            float zm = zsel[point*EE + o];
            ms[nl][o] = fmaxf(fmaf(a2o, zm, c2o), 0.f);
        }
    }
    __syncthreads();
    int nl = t & 63;
    int ob = (t >> 6) * 16;
    float acc[16];
    #pragma unroll
    for (int i = 0; i < 16; i++) acc[i] = 0.f;
    #pragma unroll 4
    for (int c = 0; c < CC; c++) {
        float mv = ms[nl][c];
        #pragma unroll
        for (int i = 0; i < 16; i++)
            acc[i] = fmaf(W3sT[c][ob+i], mv, acc[i]);
    }
    #pragma unroll
    for (int i = 0; i < 16; i++)
        out[(b*EE + ob + i)*NN + n0 + nl] = acc[i];
}

// BN3 stats over out
__global__ void k_stats3(const float* __restrict__ out) {
    __shared__ float r1[256], r2[256];
    int p = blockIdx.x;
    int o = p & 63;
    const float* base = out + (size_t)p*NN;
    int t = threadIdx.x;
    float s = 0.f, q = 0.f;
    for (int i = t; i < NN; i += 256) {
        float v = base[i];
        s += v;
        q = fmaf(v, v, q);
    }
    r1[t] = s; r2[t] = q;
    __syncthreads();
    for (int w = 128; w > 0; w >>= 1) {
        if (t < w) { r1[t] += r1[t+w]; r2[t] += r2[t+w]; }
        __syncthreads();
    }
    if (t == 0) {
        atomicAdd(&g_sum3[o], r1[0]);
        atomicAdd(&g_sumsq3[o], r2[0]);
    }
}

// BN3 + ReLU in place
__global__ void k_out(const float* __restrict__ g3, const float* __restrict__ be3,
                      float* __restrict__ out) {
    __shared__ float sa[EE], sc[EE];
    int t = threadIdx.x;
    if (t < EE) {
        float m3 = g_sum3[t] * (1.f/CNT3);
        float v3 = fmaxf(g_sumsq3[t] * (1.f/CNT3) - m3*m3, 0.f);
        float a3 = g3[t] * rsqrtf(v3 + EPSV);
        sa[t] = a3;
        sc[t] = be3[t] - a3 * m3;
    }
    __syncthreads();
    int gi = blockIdx.x * blockDim.x + t;
    int o = (gi >> 10) & 63;
    float4* out4 = (float4*)out;
    float4 v = out4[gi];
    float a = sa[o], c = sc[o];
    v.x = fmaxf(fmaf(a, v.x, c), 0.f);
    v.y = fmaxf(fmaf(a, v.y, c), 0.f);
    v.z = fmaxf(fmaf(a, v.z, c), 0.f);
    v.w = fmaxf(fmaf(a, v.w, c), 0.f);
    out4[gi] = v;
}

extern "C" void kernel_launch(void* const* d_in, const int* in_sizes, int n_in,
                              void* d_out, int out_size) {
    const float* x   = (const float*)d_in[0];
    const int*   idx = (const int*)  d_in[1];
    const float* W1  = (const float*)d_in[2];
    const float* g1  = (const float*)d_in[4];
    const float* be1 = (const float*)d_in[5];
    const float* W2  = (const float*)d_in[6];
    const float* g2  = (const float*)d_in[8];
    const float* be2 = (const float*)d_in[9];
    const float* W3  = (const float*)d_in[10];
    const float* g3  = (const float*)d_in[12];
    const float* be3 = (const float*)d_in[13];
    float* out = (float*)d_out;

    k_y1    <<<dim3(64, 8), 256>>>(x, W1);
    k_stats1<<<512, 256>>>(idx);
    k_prep  <<<2048, 256>>>(g1, be1);
    k_edge  <<<2048, 128>>>(idx, W2);   // 16 points per CTA, 2 warps per point
    k_pool3 <<<dim3(64, 8), 256>>>(W3, g2, be2, out);
    k_stats3<<<512, 256>>>(out);
    k_out   <<<2048, 256>>>(g3, be3, out);
}

// round 9
// speedup vs baseline: 2.2311x; 1.0294x over previous
#include <cuda_runtime.h>
#include <cuda_bf16.h>
#include <cstdint>

#define BB 8
#define CC 64
#define NN 4096
#define KK 16
#define EE 64
#define NPOINTS (BB*NN)            // 32768
#define CNT1 524288.0f             // B*N*K
#define CNT3 32768.0f              // B*N
#define EPSV 1e-5f

// ---- scratch (device globals: allocation-free rule) ----
__device__ float g_y1t[NPOINTS*EE];       // 8 MB  raw y1 transposed [point][c]
__device__ float g_u[NPOINTS*EE];         // 8 MB  permuted u = a1*y
__device__ float g_un[NPOINTS*EE];        // 8 MB  permuted un' = u - c1
__device__ float g_zmax[NPOINTS*EE];      // 8 MB
__device__ float g_zmin[NPOINTS*EE];      // 8 MB
__device__ float g_sum1[EE], g_sumsq1[EE];
__device__ float g_sum2[EE], g_sumsq2[EE];
__device__ float g_sum3[EE], g_sumsq3[EE];

// pack two fp32 into bf16x2 (first arg -> low half)
__device__ __forceinline__ uint32_t pack_bf2(float lo_e, float hi_e) {
    uint32_t r;
    asm("cvt.rn.bf16x2.f32 %0, %1, %2;" : "=r"(r) : "f"(hi_e), "f"(lo_e));
    return r;
}

__device__ __forceinline__ void mma16816(float d[4], const uint32_t a[4], uint32_t b0, uint32_t b1) {
    asm volatile(
        "mma.sync.aligned.m16n8k16.row.col.f32.bf16.bf16.f32 "
        "{%0,%1,%2,%3}, {%4,%5,%6,%7}, {%8,%9}, {%0,%1,%2,%3};"
        : "+f"(d[0]), "+f"(d[1]), "+f"(d[2]), "+f"(d[3])
        : "r"(a[0]), "r"(a[1]), "r"(a[2]), "r"(a[3]), "r"(b0), "r"(b1));
}

// split a packed pair (x,y) into hi (bf16) and lo (residual bf16)
__device__ __forceinline__ void split2(float x, float y, uint32_t& hi, uint32_t& lo) {
    hi = pack_bf2(x, y);
    float e0 = __uint_as_float(hi << 16);
    float e1 = __uint_as_float(hi & 0xffff0000u);
    lo = pack_bf2(x - e0, y - e1);
}

__device__ __forceinline__ uint32_t smem_u32(const void* p) {
    uint32_t a;
    asm("{ .reg .u64 t; cvta.to.shared.u64 t, %1; cvt.u32.u64 %0, t; }" : "=r"(a) : "l"(p));
    return a;
}
__device__ __forceinline__ float4 lds128(uint32_t a) {
    float4 v;
    asm volatile("ld.shared.v4.f32 {%0,%1,%2,%3}, [%4];"
                 : "=f"(v.x), "=f"(v.y), "=f"(v.z), "=f"(v.w) : "r"(a));
    return v;
}
#define CP16(d, s) asm volatile("cp.async.cg.shared.global [%0], [%1], 16;" :: "r"(d), "l"(s) : "memory")
#define CP_COMMIT() asm volatile("cp.async.commit_group;" ::: "memory")
#define CP_WAIT0()  asm volatile("cp.async.wait_group 0;" ::: "memory")

// ============================================================================
// y1t[b][n][e] = sum_c W1[e][c] * x[b][c][n];  block(0,0) zeroes accumulators
__global__ void k_y1(const float* __restrict__ x, const float* __restrict__ W1) {
    __shared__ float xs[CC][64];
    __shared__ float W1sT[CC][EE];
    int b = blockIdx.y;
    int n0 = blockIdx.x * 64;
    int t = threadIdx.x;
    if (blockIdx.x == 0 && blockIdx.y == 0 && t < EE) {
        g_sum1[t]=0.f; g_sumsq1[t]=0.f;
        g_sum2[t]=0.f; g_sumsq2[t]=0.f;
        g_sum3[t]=0.f; g_sumsq3[t]=0.f;
    }
    for (int i = t; i < CC*EE; i += 256) {
        int o = i >> 6, c = i & 63;
        W1sT[c][o] = W1[i];
    }
    for (int i = t; i < CC*64; i += 256) {
        int c = i >> 6, j = i & 63;
        xs[c][j] = x[(b*CC + c)*NN + n0 + j];
    }
    __syncthreads();
    int e = t & 63;
    int nb = (t >> 6) * 16;
    float acc[16];
    #pragma unroll
    for (int i = 0; i < 16; i++) acc[i] = 0.f;
    #pragma unroll 4
    for (int c = 0; c < CC; c++) {
        float w = W1sT[c][e];
        #pragma unroll
        for (int i = 0; i < 16; i++) acc[i] = fmaf(w, xs[c][nb+i], acc[i]);
    }
    #pragma unroll
    for (int i = 0; i < 16; i++)
        g_y1t[(b*NN + n0 + nb + i)*EE + e] = acc[i];
}

// BN1 stats over d = y_j - y_n (float4 gathers, idx shared via shfl)
__global__ void k_stats1(const int* __restrict__ idx) {
    __shared__ float4 red_s[16][16];
    __shared__ float4 red_q[16][16];
    int t = threadIdx.x;
    int c4 = t & 15, g = t >> 4;       // 16 groups of 16 threads (half-warps)
    float4 s = make_float4(0.f,0.f,0.f,0.f);
    float4 q = make_float4(0.f,0.f,0.f,0.f);
    int p0 = blockIdx.x * 64;
    #pragma unroll 1
    for (int pl = 0; pl < 4; pl++) {
        int point = p0 + g*4 + pl;
        int brow = point & ~(NN-1);
        int jown = idx[point*KK + c4];   // lane c4 holds neighbor k=c4
        float4 yn = *(const float4*)(g_y1t + (size_t)point*EE + c4*4);
        #pragma unroll
        for (int k = 0; k < KK; k++) {
            int j = __shfl_sync(0xffffffffu, jown, ((t & 31) & 16) | k, 32);
            float4 yj = *(const float4*)(g_y1t + (size_t)(brow + j)*EE + c4*4);
            float dx = yj.x - yn.x, dy = yj.y - yn.y, dz = yj.z - yn.z, dw = yj.w - yn.w;
            s.x += dx; s.y += dy; s.z += dz; s.w += dw;
            q.x = fmaf(dx, dx, q.x); q.y = fmaf(dy, dy, q.y);
            q.z = fmaf(dz, dz, q.z); q.w = fmaf(dw, dw, q.w);
        }
    }
    red_s[g][c4] = s;
    red_q[g][c4] = q;
    __syncthreads();
    if (t < 64) {
        float ss = 0.f, qq = 0.f;
        #pragma unroll
        for (int gg = 0; gg < 16; gg++) {
            ss += ((const float*)&red_s[gg][t >> 2])[t & 3];
            qq += ((const float*)&red_q[gg][t >> 2])[t & 3];
        }
        atomicAdd(&g_sum1[t], ss);
        atomicAdd(&g_sumsq1[t], qq);
    }
}

// fold BN1 into y with CHANNEL PERMUTATION:
// phys float4 slot (blk, q) holds orig channels {blk*16+2q, +1, blk*16+2q+8, +9}
__global__ void k_prep(const float* __restrict__ g1, const float* __restrict__ be1) {
    int i = blockIdx.x * blockDim.x + threadIdx.x;   // phys float4 id, 524288 total
    int point = i >> 4;
    int blk = (i >> 2) & 3;
    int q = i & 3;
    int cb = blk*16 + q*2;
    int co[4] = {cb, cb+1, cb+8, cb+9};
    float a[4], cv[4];
    #pragma unroll
    for (int j = 0; j < 4; j++) {
        int c = co[j];
        float m1 = g_sum1[c] * (1.f/CNT1);
        float v1 = fmaxf(g_sumsq1[c] * (1.f/CNT1) - m1*m1, 0.f);
        a[j] = g1[c] * rsqrtf(v1 + EPSV);
        cv[j] = be1[c] - a[j] * m1;
    }
    const float* yrow = g_y1t + (size_t)point*EE + blk*16;
    float2 A = *(const float2*)(yrow + q*2);
    float2 B = *(const float2*)(yrow + q*2 + 8);
    float4 u;
    u.x = A.x*a[0]; u.y = A.y*a[1]; u.z = B.x*a[2]; u.w = B.y*a[3];
    float4 un;
    un.x = u.x - cv[0]; un.y = u.y - cv[1]; un.z = u.z - cv[2]; un.w = u.w - cv[3];
    ((float4*)g_u)[i]  = u;
    ((float4*)g_un)[i] = un;
}

// ============================================================================
// Main pass via mma.sync bf16 (split-bf16, 3 terms), operand-swapped,
// with cp.async.cg double-buffered THREAD-LOCAL gather staging:
// each lane stages and consumes exactly its own 12 x 16B chunks; no barriers.
#define EDGE_STAGE_BYTES (12*512)              // 6 KB per stage
#define EDGE_WARP_BYTES  (2*EDGE_STAGE_BYTES)  // 12 KB per warp
#define EDGE_SMEM (4*EDGE_WARP_BYTES + 512)    // 49664 B

__device__ __forceinline__ void stage_point(uint32_t dlane, int qoff,
                                            int p, int j0, int j1) {
    int base = p & ~(NN-1);
    const char* cen = (const char*)g_un + (((size_t)p) << 8) + qoff;
    const char* r0  = (const char*)g_u  + (((size_t)(base + j0)) << 8) + qoff;
    const char* r1  = (const char*)g_u  + (((size_t)(base + j1)) << 8) + qoff;
    #pragma unroll
    for (int ks = 0; ks < 4; ks++) {
        CP16(dlane + (ks*3+0)*512, cen + ks*64);
        CP16(dlane + (ks*3+1)*512, r0  + ks*64);
        CP16(dlane + (ks*3+2)*512, r1  + ks*64);
    }
    CP_COMMIT();
}

__global__ void __launch_bounds__(128, 4) k_edge(const int* __restrict__ idx,
                                                 const float* __restrict__ W2) {
    extern __shared__ char esm[];
    float* sm_s = (float*)(esm + 4*EDGE_WARP_BYTES);
    float* sm_q = sm_s + 64;
    int t = threadIdx.x;
    int lane = t & 31, w = t >> 5;
    int g = lane >> 2, q = lane & 3;

    if (t < 64) { sm_s[t] = 0.f; sm_q[t] = 0.f; }

    // A = W2 fragments for this warp's 2 m-tiles (32 output channels), resident
    int mtb = (w & 1) * 2;
    uint32_t Ahi[2][4][4], Alo[2][4][4];
    #pragma unroll
    for (int mi = 0; mi < 2; mi++) {
        int o0 = (mtb + mi)*16 + g;
        #pragma unroll
        for (int ks = 0; ks < 4; ks++) {
            int cb = ks*16 + q*2;
            const float* r0 = W2 + o0*64 + cb;
            const float* r1 = W2 + (o0+8)*64 + cb;
            float2 a00 = *(const float2*)(r0);
            float2 a01 = *(const float2*)(r0 + 8);
            float2 a10 = *(const float2*)(r1);
            float2 a11 = *(const float2*)(r1 + 8);
            split2(a00.x, a00.y, Ahi[mi][ks][0], Alo[mi][ks][0]);
            split2(a10.x, a10.y, Ahi[mi][ks][1], Alo[mi][ks][1]);
            split2(a01.x, a01.y, Ahi[mi][ks][2], Alo[mi][ks][2]);
            split2(a11.x, a11.y, Ahi[mi][ks][3], Alo[mi][ks][3]);
        }
    }

    uint32_t dlane = smem_u32(esm) + w*EDGE_WARP_BYTES + lane*16;
    int qoff = q*16;
    int pslot = w >> 1;
    int pbase = blockIdx.x * 16 + pslot * 8;

    float sums[4], sumq[4];
    #pragma unroll
    for (int i = 0; i < 4; i++) { sums[i] = 0.f; sumq[i] = 0.f; }

    // prologue: stage point 0, prefetch idx for point 1
    int j0c = idx[pbase*KK + g],       j1c = idx[pbase*KK + 8 + g];
    int j0n = idx[(pbase+1)*KK + g],   j1n = idx[(pbase+1)*KK + 8 + g];
    stage_point(dlane, qoff, pbase, j0c, j1c);

    __syncthreads();   // sm_s/sm_q init visible before end-of-kernel atomics

    #pragma unroll 1
    for (int pi = 0; pi < 8; pi++) {
        int p = pbase + pi;
        uint32_t buf = dlane + (pi & 1) * EDGE_STAGE_BYTES;
        CP_WAIT0();                          // buf(pi) ready (staged last iter)

        // prefetch idx for pi+2 (clamped; covered by this point's MMA latency)
        int pn2 = pbase + ((pi + 2 < 8) ? pi + 2 : 7);
        int j0f = idx[pn2*KK + g], j1f = idx[pn2*KK + 8 + g];
        // stage pi+1 into the other buffer; flies during MMA+epilogue below
        if (pi < 7)
            stage_point(dlane + ((pi+1) & 1) * EDGE_STAGE_BYTES, qoff, p + 1, j0n, j1n);

        float D[2][2][4];
        #pragma unroll
        for (int mi = 0; mi < 2; mi++)
            #pragma unroll
            for (int nt = 0; nt < 2; nt++)
                #pragma unroll
                for (int i = 0; i < 4; i++) D[mi][nt][i] = 0.f;

        #pragma unroll
        for (int ks = 0; ks < 4; ks++) {
            float4 nf = lds128(buf + (ks*3+0)*512);
            float4 x0 = lds128(buf + (ks*3+1)*512);
            float4 x1 = lds128(buf + (ks*3+2)*512);
            uint32_t bh00, bl00, bh01, bl01;
            uint32_t bh10, bl10, bh11, bl11;
            split2(fmaxf(x0.x - nf.x, 0.f), fmaxf(x0.y - nf.y, 0.f), bh00, bl00);
            split2(fmaxf(x0.z - nf.z, 0.f), fmaxf(x0.w - nf.w, 0.f), bh01, bl01);
            split2(fmaxf(x1.x - nf.x, 0.f), fmaxf(x1.y - nf.y, 0.f), bh10, bl10);
            split2(fmaxf(x1.z - nf.z, 0.f), fmaxf(x1.w - nf.w, 0.f), bh11, bl11);
            #pragma unroll
            for (int mi = 0; mi < 2; mi++) {
                mma16816(D[mi][0], Ahi[mi][ks], bh00, bh01);
                mma16816(D[mi][0], Alo[mi][ks], bh00, bh01);
                mma16816(D[mi][0], Ahi[mi][ks], bl00, bl01);
                mma16816(D[mi][1], Ahi[mi][ks], bh10, bh11);
                mma16816(D[mi][1], Alo[mi][ks], bh10, bh11);
                mma16816(D[mi][1], Ahi[mi][ks], bl10, bl11);
            }
        }

        // reduce over neighbors: in-thread, then shfl over q
        #pragma unroll
        for (int mi = 0; mi < 2; mi++) {
            float d00 = D[mi][0][0], d01 = D[mi][0][1];
            float d10 = D[mi][1][0], d11 = D[mi][1][1];
            float e00 = D[mi][0][2], e01 = D[mi][0][3];
            float e10 = D[mi][1][2], e11 = D[mi][1][3];
            sums[mi*2]   += (d00 + d01) + (d10 + d11);
            sums[mi*2+1] += (e00 + e01) + (e10 + e11);
            sumq[mi*2]   = fmaf(d00,d00, fmaf(d01,d01, fmaf(d10,d10, fmaf(d11,d11, sumq[mi*2]))));
            sumq[mi*2+1] = fmaf(e00,e00, fmaf(e01,e01, fmaf(e10,e10, fmaf(e11,e11, sumq[mi*2+1]))));
            float mx0 = fmaxf(fmaxf(d00, d01), fmaxf(d10, d11));
            float mn0 = fminf(fminf(d00, d01), fminf(d10, d11));
            float mx1 = fmaxf(fmaxf(e00, e01), fmaxf(e10, e11));
            float mn1 = fminf(fminf(e00, e01), fminf(e10, e11));
            #pragma unroll
            for (int off = 1; off < 4; off <<= 1) {
                mx0 = fmaxf(mx0, __shfl_xor_sync(0xffffffffu, mx0, off));
                mn0 = fminf(mn0, __shfl_xor_sync(0xffffffffu, mn0, off));
                mx1 = fmaxf(mx1, __shfl_xor_sync(0xffffffffu, mx1, off));
                mn1 = fminf(mn1, __shfl_xor_sync(0xffffffffu, mn1, off));
            }
            if (q == 0) {
                int ch = (mtb + mi)*16 + g;
                g_zmax[(size_t)p*EE + ch]     = mx0;
                g_zmax[(size_t)p*EE + ch + 8] = mx1;
                g_zmin[(size_t)p*EE + ch]     = mn0;
                g_zmin[(size_t)p*EE + ch + 8] = mn1;
            }
        }
        j0n = j0f; j1n = j1f;
    }

    // BN2 sums: shfl-reduce over q, stage in smem, one global atomic per channel
    #pragma unroll
    for (int i = 0; i < 4; i++) {
        float s = sums[i], qq = sumq[i];
        #pragma unroll
        for (int off = 1; off < 4; off <<= 1) {
            s  += __shfl_xor_sync(0xffffffffu, s, off);
            qq += __shfl_xor_sync(0xffffffffu, qq, off);
        }
        if (q == 0) {
            int ch = (mtb + (i >> 1))*16 + g + (i & 1)*8;
            atomicAdd(&sm_s[ch], s);
            atomicAdd(&sm_q[ch], qq);
        }
    }
    __syncthreads();
    if (t < 64) {
        atomicAdd(&g_sum2[t],   sm_s[t]);
        atomicAdd(&g_sumsq2[t], sm_q[t]);
    }
}

// ============================================================================
// pooled m = relu(a2*z_sel+c2); z3 = W3@m -> out
__global__ void k_pool3(const float* __restrict__ W3,
                        const float* __restrict__ g2,
                        const float* __restrict__ be2,
                        float* __restrict__ out) {
    __shared__ float ms[64][65];
    __shared__ float W3sT[CC][EE];
    int b = blockIdx.y;
    int n0 = blockIdx.x * 64;
    int t = threadIdx.x;
    for (int i = t; i < CC*EE; i += 256) {
        int o = i >> 6, c = i & 63;
        W3sT[c][o] = W3[i];
    }
    {
        int o = t & 63;
        int ng = t >> 6;
        float m2 = g_sum2[o] * (1.f/CNT1);
        float v2 = fmaxf(g_sumsq2[o] * (1.f/CNT1) - m2*m2, 0.f);
        float a2o = g2[o] * rsqrtf(v2 + EPSV);
        float c2o = be2[o] - a2o * m2;
        const float* zsel = (a2o >= 0.f) ? g_zmax : g_zmin;
        for (int nl = ng; nl < 64; nl += 4) {
            int point = b*NN + n0 + nl;
            float zm = zsel[point*EE + o];
            ms[nl][o] = fmaxf(fmaf(a2o, zm, c2o), 0.f);
        }
    }
    __syncthreads();
    int nl = t & 63;
    int ob = (t >> 6) * 16;
    float acc[16];
    #pragma unroll
    for (int i = 0; i < 16; i++) acc[i] = 0.f;
    #pragma unroll 4
    for (int c = 0; c < CC; c++) {
        float mv = ms[nl][c];
        #pragma unroll
        for (int i = 0; i < 16; i++)
            acc[i] = fmaf(W3sT[c][ob+i], mv, acc[i]);
    }
    #pragma unroll
    for (int i = 0; i < 16; i++)
        out[(b*EE + ob + i)*NN + n0 + nl] = acc[i];
}

// BN3 stats over out
__global__ void k_stats3(const float* __restrict__ out) {
    __shared__ float r1[256], r2[256];
    int p = blockIdx.x;
    int o = p & 63;
    const float* base = out + (size_t)p*NN;
    int t = threadIdx.x;
    float s = 0.f, q = 0.f;
    for (int i = t; i < NN; i += 256) {
        float v = base[i];
        s += v;
        q = fmaf(v, v, q);
    }
    r1[t] = s; r2[t] = q;
    __syncthreads();
    for (int w = 128; w > 0; w >>= 1) {
        if (t < w) { r1[t] += r1[t+w]; r2[t] += r2[t+w]; }
        __syncthreads();
    }
    if (t == 0) {
        atomicAdd(&g_sum3[o], r1[0]);
        atomicAdd(&g_sumsq3[o], r2[0]);
    }
}

// BN3 + ReLU in place
__global__ void k_out(const float* __restrict__ g3, const float* __restrict__ be3,
                      float* __restrict__ out) {
    __shared__ float sa[EE], sc[EE];
    int t = threadIdx.x;
    if (t < EE) {
        float m3 = g_sum3[t] * (1.f/CNT3);
        float v3 = fmaxf(g_sumsq3[t] * (1.f/CNT3) - m3*m3, 0.f);
        float a3 = g3[t] * rsqrtf(v3 + EPSV);
        sa[t] = a3;
        sc[t] = be3[t] - a3 * m3;
    }
    __syncthreads();
    int gi = blockIdx.x * blockDim.x + t;
    int o = (gi >> 10) & 63;
    float4* out4 = (float4*)out;
    float4 v = out4[gi];
    float a = sa[o], c = sc[o];
    v.x = fmaxf(fmaf(a, v.x, c), 0.f);
    v.y = fmaxf(fmaf(a, v.y, c), 0.f);
    v.z = fmaxf(fmaf(a, v.z, c), 0.f);
    v.w = fmaxf(fmaf(a, v.w, c), 0.f);
    out4[gi] = v;
}

extern "C" void kernel_launch(void* const* d_in, const int* in_sizes, int n_in,
                              void* d_out, int out_size) {
    const float* x   = (const float*)d_in[0];
    const int*   idx = (const int*)  d_in[1];
    const float* W1  = (const float*)d_in[2];
    const float* g1  = (const float*)d_in[4];
    const float* be1 = (const float*)d_in[5];
    const float* W2  = (const float*)d_in[6];
    const float* g2  = (const float*)d_in[8];
    const float* be2 = (const float*)d_in[9];
    const float* W3  = (const float*)d_in[10];
    const float* g3  = (const float*)d_in[12];
    const float* be3 = (const float*)d_in[13];
    float* out = (float*)d_out;

    cudaFuncSetAttribute(k_edge, cudaFuncAttributeMaxDynamicSharedMemorySize, EDGE_SMEM);

    k_y1    <<<dim3(64, 8), 256>>>(x, W1);
    k_stats1<<<512, 256>>>(idx);
    k_prep  <<<2048, 256>>>(g1, be1);
    k_edge  <<<2048, 128, EDGE_SMEM>>>(idx, W2);
    k_pool3 <<<dim3(64, 8), 256>>>(W3, g2, be2, out);
    k_stats3<<<512, 256>>>(out);
    k_out   <<<2048, 256>>>(g3, be3, out);
}